// round 5
// baseline (speedup 1.0000x reference)
#include <cuda_runtime.h>

#define N_NODES 100000
#define N_EDGES 1600000
#define IN_CH   128
#define HID     32
#define HID2    64
#define OUT_CH  64
#define N_LAYERS 16

#define EPS_MSG 1e-7f
#define EPS_SM  1e-16f
#define EPS_BN  1e-5f

#define FULL 0xffffffffu
#define NBLK_MLP1 1184

// ---------------- scratch (static device globals; no allocation) -------------
__device__ float        g_h  [N_NODES * HID];   // current node features
__device__ unsigned int g_mx [N_NODES * HID];   // per-dst channel max (float bits)
__device__ float        g_den[N_NODES * HID];   // softmax denominator (sum e)
__device__ float        g_num[N_NODES * HID];   // softmax numerator   (sum e*m)
__device__ float        g_z  [N_NODES * HID2];  // hidden MLP activations
__device__ float        g_psum[NBLK_MLP1 * HID2];  // BN partial sums
__device__ float        g_psq [NBLK_MLP1 * HID2];  // BN partial sum-squares
__device__ float        g_scale[HID2];
__device__ float        g_shift[HID2];
__device__ int          g_is64;                 // 1 if edge_index is int64

// ---------------- detect edge_index dtype ------------------------------------
// int64 little-endian with values < 2^31  =>  every odd 32-bit word is 0.
// int32 layout => odd words are random node indices (all-zero prob ~ 0).
__global__ void k_detect(const int* __restrict__ ei32) {
    __shared__ int any;
    if (threadIdx.x == 0) any = 0;
    __syncthreads();
    int v = ei32[2 * threadIdx.x + 1] | ei32[2 * (threadIdx.x + 1024) + 1];
    if (v != 0) any = 1;
    __syncthreads();
    if (threadIdx.x == 0) g_is64 = (any == 0) ? 1 : 0;
}

__device__ __forceinline__ void load_edge(const int* __restrict__ ei32,
                                          int e, int& src, int& dst) {
    if (g_is64) {
        src = ei32[2 * e];
        dst = ei32[2 * (N_EDGES + e)];
    } else {
        src = ei32[e];
        dst = ei32[N_EDGES + e];
    }
    src = min(max(src, 0), N_NODES - 1);
    dst = min(max(dst, 0), N_NODES - 1);
}

// ---------------- input projection: h = x @ w0 + b0; zero accumulators -------
__global__ void k_input(const float* __restrict__ x,
                        const float* __restrict__ w0,
                        const float* __restrict__ b0) {
    __shared__ float sw[IN_CH * HID];
    __shared__ float sb[HID];
    int tid = threadIdx.x;
    for (int i = tid; i < IN_CH * HID; i += 256) sw[i] = w0[i];
    if (tid < HID) sb[tid] = b0[tid];
    __syncthreads();

    int n = blockIdx.x * 8 + (tid >> 5);
    int lane = tid & 31;
    if (n >= N_NODES) return;

    const float* xr = x + (long long)n * IN_CH;
    float acc = sb[lane];
#pragma unroll
    for (int k0 = 0; k0 < IN_CH; k0 += 32) {
        float xv = xr[k0 + lane];
#pragma unroll
        for (int j = 0; j < 32; j++) {
            float xb = __shfl_sync(FULL, xv, j);
            acc = fmaf(xb, sw[(k0 + j) * HID + lane], acc);
        }
    }
    int base = n * HID + lane;
    g_h[base]  = acc;
    g_mx[base] = 0u;    // all messages > 0, so 0-bits is a safe identity for max
    g_den[base] = 0.f;
    g_num[base] = 0.f;
}

// ---------------- edge pass A: per-dst per-channel max of m ------------------
__global__ void k_edge_max(const int* __restrict__ ei32) {
    int t = blockIdx.x * blockDim.x + threadIdx.x;
    int e = t >> 5;
    if (e >= N_EDGES) return;
    int lane = t & 31;
    int src, dst;
    load_edge(ei32, e, src, dst);
    float m = fmaxf(g_h[src * HID + lane], 0.f) + EPS_MSG;   // m > 0 always
    atomicMax(&g_mx[dst * HID + lane], __float_as_uint(m));
}

// ---------------- edge pass B: den += e, num += e*m --------------------------
__global__ void k_edge_sum(const int* __restrict__ ei32) {
    int t = blockIdx.x * blockDim.x + threadIdx.x;
    int e = t >> 5;
    if (e >= N_EDGES) return;
    int lane = t & 31;
    int src, dst;
    load_edge(ei32, e, src, dst);
    float m = fmaxf(g_h[src * HID + lane], 0.f) + EPS_MSG;
    float mx = __uint_as_float(g_mx[dst * HID + lane]);
    float ex = __expf(m - mx);
    atomicAdd(&g_den[dst * HID + lane], ex);
    atomicAdd(&g_num[dst * HID + lane], ex * m);
}

// ---------------- node MLP part 1: z = (agg + h) @ w1 + b1; BN partials ------
__global__ void k_mlp1(const float* __restrict__ w1,
                       const float* __restrict__ b1) {
    __shared__ float sw[HID * HID2];
    __shared__ float sb[HID2];
    __shared__ float bsum[HID2], bsq[HID2];
    int tid = threadIdx.x;
    for (int i = tid; i < HID * HID2; i += 256) sw[i] = w1[i];
    if (tid < HID2) { sb[tid] = b1[tid]; bsum[tid] = 0.f; bsq[tid] = 0.f; }
    __syncthreads();

    int lane = tid & 31;
    int warp = blockIdx.x * 8 + (tid >> 5);
    int nwarps = gridDim.x * 8;
    float s0 = 0.f, q0 = 0.f, s1 = 0.f, q1 = 0.f;

    for (int n = warp; n < N_NODES; n += nwarps) {
        int base = n * HID + lane;
        float ov = g_num[base] / (g_den[base] + EPS_SM) + g_h[base];
        float a0 = sb[lane], a1 = sb[lane + 32];
#pragma unroll
        for (int j = 0; j < 32; j++) {
            float ob = __shfl_sync(FULL, ov, j);
            a0 = fmaf(ob, sw[j * HID2 + lane],      a0);
            a1 = fmaf(ob, sw[j * HID2 + lane + 32], a1);
        }
        g_z[n * HID2 + lane]      = a0;
        g_z[n * HID2 + lane + 32] = a1;
        s0 += a0; q0 += a0 * a0;
        s1 += a1; q1 += a1 * a1;
    }
    atomicAdd(&bsum[lane],      s0); atomicAdd(&bsq[lane],      q0);
    atomicAdd(&bsum[lane + 32], s1); atomicAdd(&bsq[lane + 32], q1);
    __syncthreads();
    if (tid < HID2) {
        g_psum[blockIdx.x * HID2 + tid] = bsum[tid];
        g_psq [blockIdx.x * HID2 + tid] = bsq[tid];
    }
}

// ---------------- BN finalize: reduce partials; fold into scale/shift --------
__global__ void k_bn(const float* __restrict__ gamma,
                     const float* __restrict__ beta) {
    __shared__ float rs[256], rq[256];
    int c = blockIdx.x;
    int tid = threadIdx.x;
    float s = 0.f, q = 0.f;
    for (int b = tid; b < NBLK_MLP1; b += 256) {
        s += g_psum[b * HID2 + c];
        q += g_psq [b * HID2 + c];
    }
    rs[tid] = s; rq[tid] = q;
    __syncthreads();
    for (int o = 128; o > 0; o >>= 1) {
        if (tid < o) { rs[tid] += rs[tid + o]; rq[tid] += rq[tid + o]; }
        __syncthreads();
    }
    if (tid == 0) {
        float mean = rs[0] / (float)N_NODES;
        float var  = rq[0] / (float)N_NODES - mean * mean;
        float rstd = rsqrtf(var + EPS_BN);
        float sc = gamma[c] * rstd;
        g_scale[c] = sc;
        g_shift[c] = beta[c] - mean * sc;
    }
}

// ---------------- node MLP part 2: h = relu(relu(BN(z)) @ w2 + b2) -----------
// also zeroes the per-node accumulators for the next layer's edge passes
__global__ void k_mlp2(const float* __restrict__ w2,
                       const float* __restrict__ b2) {
    __shared__ float sw[HID2 * HID];
    __shared__ float sb[HID];
    __shared__ float ssc[HID2], ssh[HID2];
    int tid = threadIdx.x;
    for (int i = tid; i < HID2 * HID; i += 256) sw[i] = w2[i];
    if (tid < HID) sb[tid] = b2[tid];
    if (tid < HID2) { ssc[tid] = g_scale[tid]; ssh[tid] = g_shift[tid]; }
    __syncthreads();

    int n = blockIdx.x * 8 + (tid >> 5);
    int lane = tid & 31;
    if (n >= N_NODES) return;

    float y0 = fmaxf(fmaf(g_z[n * HID2 + lane],      ssc[lane],      ssh[lane]),      0.f);
    float y1 = fmaxf(fmaf(g_z[n * HID2 + lane + 32], ssc[lane + 32], ssh[lane + 32]), 0.f);
    float acc = sb[lane];
#pragma unroll
    for (int j = 0; j < 32; j++) {
        acc = fmaf(__shfl_sync(FULL, y0, j), sw[j * HID + lane],        acc);
        acc = fmaf(__shfl_sync(FULL, y1, j), sw[(j + 32) * HID + lane], acc);
    }
    int base = n * HID + lane;
    g_h[base]  = fmaxf(acc, 0.f);   // outer relu from the layer loop
    g_mx[base] = 0u;
    g_den[base] = 0.f;
    g_num[base] = 0.f;
}

// ---------------- output projection: out = h @ w16 + b16 ---------------------
__global__ void k_final(const float* __restrict__ w16,
                        const float* __restrict__ b16,
                        float* __restrict__ out) {
    __shared__ float sw[HID * OUT_CH];
    __shared__ float sb[OUT_CH];
    int tid = threadIdx.x;
    for (int i = tid; i < HID * OUT_CH; i += 256) sw[i] = w16[i];
    if (tid < OUT_CH) sb[tid] = b16[tid];
    __syncthreads();

    int n = blockIdx.x * 8 + (tid >> 5);
    int lane = tid & 31;
    if (n >= N_NODES) return;

    float hv = g_h[n * HID + lane];
    float a0 = sb[lane], a1 = sb[lane + 32];
#pragma unroll
    for (int j = 0; j < 32; j++) {
        float hb = __shfl_sync(FULL, hv, j);
        a0 = fmaf(hb, sw[j * OUT_CH + lane],      a0);
        a1 = fmaf(hb, sw[j * OUT_CH + lane + 32], a1);
    }
    out[n * OUT_CH + lane]      = a0;
    out[n * OUT_CH + lane + 32] = a1;
}

// -----------------------------------------------------------------------------
extern "C" void kernel_launch(void* const* d_in, const int* in_sizes, int n_in,
                              void* d_out, int out_size) {
    const float* x      = (const float*)d_in[0];
    const int*   ei32   = (const int*)d_in[1];     // int32 OR int64 (detected)
    const float* w0     = (const float*)d_in[2];
    const float* b0     = (const float*)d_in[3];
    const float* lin1_w = (const float*)d_in[4];
    const float* lin1_b = (const float*)d_in[5];
    const float* gamma  = (const float*)d_in[6];
    const float* beta   = (const float*)d_in[7];
    const float* lin2_w = (const float*)d_in[8];
    const float* lin2_b = (const float*)d_in[9];
    const float* w16    = (const float*)d_in[10];
    const float* b16    = (const float*)d_in[11];
    float* out = (float*)d_out;

    const int nodeBlocks = (N_NODES + 7) / 8;                  // warp per node
    const int edgeBlocks = (N_EDGES * 32 + 255) / 256;         // warp per edge

    k_detect<<<1, 1024>>>(ei32);
    k_input<<<nodeBlocks, 256>>>(x, w0, b0);
    for (int i = 0; i < N_LAYERS; i++) {
        k_edge_max<<<edgeBlocks, 256>>>(ei32);
        k_edge_sum<<<edgeBlocks, 256>>>(ei32);
        k_mlp1<<<NBLK_MLP1, 256>>>(lin1_w + i * HID * HID2, lin1_b + i * HID2);
        k_bn<<<HID2, 256>>>(gamma + i * HID2, beta + i * HID2);
        k_mlp2<<<nodeBlocks, 256>>>(lin2_w + i * HID2 * HID, lin2_b + i * HID);
    }
    k_final<<<nodeBlocks, 256>>>(w16, b16, out);
}

// round 6
// speedup vs baseline: 3.1327x; 3.1327x over previous
#include <cuda_runtime.h>

#define N_NODES 100000
#define N_EDGES 1600000
#define IN_CH   128
#define HID     32
#define HID2    64
#define OUT_CH  64
#define N_LAYERS 16

#define EPS_MSG 1e-7f
#define EPS_SM  1e-16f
#define EPS_BN  1e-5f

#define FULL 0xffffffffu
#define NBLK_MLP1 1184
#define E_PER 4   // edges per warp in the edge pass (1.6M % 4 == 0)

// ---------------- scratch (static device globals; no allocation) -------------
__device__ float  g_h [N_NODES * HID];    // current node features
__device__ float2 g_dn[N_NODES * HID];    // (den, num) softmax accumulators
__device__ float  g_z [N_NODES * HID2];   // hidden MLP activations
__device__ float  g_psum[NBLK_MLP1 * HID2];
__device__ float  g_psq [NBLK_MLP1 * HID2];
__device__ float  g_scale[HID2];
__device__ float  g_shift[HID2];
__device__ int    g_is64;                 // 1 if edge_index is int64

// ---------------- detect edge_index dtype ------------------------------------
// int64 little-endian with values < 2^31 => every odd 32-bit word is 0.
__global__ void k_detect(const int* __restrict__ ei32) {
    __shared__ int any;
    if (threadIdx.x == 0) any = 0;
    __syncthreads();
    int v = ei32[2 * threadIdx.x + 1] | ei32[2 * (threadIdx.x + 1024) + 1];
    if (v != 0) any = 1;
    __syncthreads();
    if (threadIdx.x == 0) g_is64 = (any == 0) ? 1 : 0;
}

// ---------------- input projection: h = x @ w0 + b0; zero accumulators -------
__global__ void k_input(const float* __restrict__ x,
                        const float* __restrict__ w0,
                        const float* __restrict__ b0) {
    __shared__ float sw[IN_CH * HID];
    __shared__ float sb[HID];
    int tid = threadIdx.x;
    for (int i = tid; i < IN_CH * HID; i += 256) sw[i] = w0[i];
    if (tid < HID) sb[tid] = b0[tid];
    __syncthreads();

    int n = blockIdx.x * 8 + (tid >> 5);
    int lane = tid & 31;
    if (n >= N_NODES) return;

    const float* xr = x + (long long)n * IN_CH;
    float acc = sb[lane];
#pragma unroll
    for (int k0 = 0; k0 < IN_CH; k0 += 32) {
        float xv = xr[k0 + lane];
#pragma unroll
        for (int j = 0; j < 32; j++) {
            float xb = __shfl_sync(FULL, xv, j);
            acc = fmaf(xb, sw[(k0 + j) * HID + lane], acc);
        }
    }
    int base = n * HID + lane;
    g_h[base]  = acc;
    g_dn[base] = make_float2(0.f, 0.f);
}

// ---------------- single edge pass: den += e^m, num += e^m * m ---------------
// No max subtraction: m = relu(h)+eps is O(10) at most (BN renormalizes every
// layer), so exp(m) is far from overflow and num/den is shift-invariant.
__global__ void k_edge(const int* __restrict__ ei32) {
    int w = blockIdx.x * (blockDim.x >> 5) + (threadIdx.x >> 5);
    int lane = threadIdx.x & 31;
    int e0 = w * E_PER;
    if (e0 >= N_EDGES) return;

    int is64 = g_is64;
    int srcs[E_PER], dsts[E_PER];
#pragma unroll
    for (int k = 0; k < E_PER; k++) {
        int e = e0 + k;
        int s, d;
        if (is64) { s = __ldg(&ei32[2 * e]);  d = __ldg(&ei32[2 * (N_EDGES + e)]); }
        else      { s = __ldg(&ei32[e]);      d = __ldg(&ei32[N_EDGES + e]); }
        srcs[k] = min(max(s, 0), N_NODES - 1);
        dsts[k] = min(max(d, 0), N_NODES - 1);
    }

    float m[E_PER];
#pragma unroll
    for (int k = 0; k < E_PER; k++)
        m[k] = fmaxf(g_h[srcs[k] * HID + lane], 0.f) + EPS_MSG;

#pragma unroll
    for (int k = 0; k < E_PER; k++) {
        float ex = __expf(m[k]);
        float2* p = &g_dn[dsts[k] * HID + lane];
        asm volatile("red.global.add.v2.f32 [%0], {%1, %2};"
                     :: "l"(p), "f"(ex), "f"(ex * m[k]) : "memory");
    }
}

// ---------------- node MLP part 1: z = (agg + h) @ w1 + b1; BN partials ------
__global__ void k_mlp1(const float* __restrict__ w1,
                       const float* __restrict__ b1) {
    __shared__ float sw[HID * HID2];
    __shared__ float sb[HID2];
    __shared__ float bsum[HID2], bsq[HID2];
    int tid = threadIdx.x;
    for (int i = tid; i < HID * HID2; i += 256) sw[i] = w1[i];
    if (tid < HID2) { sb[tid] = b1[tid]; bsum[tid] = 0.f; bsq[tid] = 0.f; }
    __syncthreads();

    int lane = tid & 31;
    int warp = blockIdx.x * 8 + (tid >> 5);
    int nwarps = gridDim.x * 8;
    float s0 = 0.f, q0 = 0.f, s1 = 0.f, q1 = 0.f;

    for (int n = warp; n < N_NODES; n += nwarps) {
        int base = n * HID + lane;
        float2 dn = g_dn[base];
        float ov = dn.y / (dn.x + EPS_SM) + g_h[base];
        float a0 = sb[lane], a1 = sb[lane + 32];
#pragma unroll
        for (int j = 0; j < 32; j++) {
            float ob = __shfl_sync(FULL, ov, j);
            a0 = fmaf(ob, sw[j * HID2 + lane],      a0);
            a1 = fmaf(ob, sw[j * HID2 + lane + 32], a1);
        }
        g_z[n * HID2 + lane]      = a0;
        g_z[n * HID2 + lane + 32] = a1;
        s0 += a0; q0 += a0 * a0;
        s1 += a1; q1 += a1 * a1;
    }
    atomicAdd(&bsum[lane],      s0); atomicAdd(&bsq[lane],      q0);
    atomicAdd(&bsum[lane + 32], s1); atomicAdd(&bsq[lane + 32], q1);
    __syncthreads();
    if (tid < HID2) {
        g_psum[blockIdx.x * HID2 + tid] = bsum[tid];
        g_psq [blockIdx.x * HID2 + tid] = bsq[tid];
    }
}

// ---------------- BN finalize: reduce partials; fold into scale/shift --------
__global__ void k_bn(const float* __restrict__ gamma,
                     const float* __restrict__ beta) {
    __shared__ float rs[256], rq[256];
    int c = blockIdx.x;
    int tid = threadIdx.x;
    float s = 0.f, q = 0.f;
    for (int b = tid; b < NBLK_MLP1; b += 256) {
        s += g_psum[b * HID2 + c];
        q += g_psq [b * HID2 + c];
    }
    rs[tid] = s; rq[tid] = q;
    __syncthreads();
    for (int o = 128; o > 0; o >>= 1) {
        if (tid < o) { rs[tid] += rs[tid + o]; rq[tid] += rq[tid + o]; }
        __syncthreads();
    }
    if (tid == 0) {
        float mean = rs[0] / (float)N_NODES;
        float var  = rq[0] / (float)N_NODES - mean * mean;
        float rstd = rsqrtf(var + EPS_BN);
        float sc = gamma[c] * rstd;
        g_scale[c] = sc;
        g_shift[c] = beta[c] - mean * sc;
    }
}

// ---------------- node MLP part 2: h = relu(relu(BN(z)) @ w2 + b2) -----------
// also zeroes the per-node accumulators for the next layer's edge pass
__global__ void k_mlp2(const float* __restrict__ w2,
                       const float* __restrict__ b2) {
    __shared__ float sw[HID2 * HID];
    __shared__ float sb[HID];
    __shared__ float ssc[HID2], ssh[HID2];
    int tid = threadIdx.x;
    for (int i = tid; i < HID2 * HID; i += 256) sw[i] = w2[i];
    if (tid < HID) sb[tid] = b2[tid];
    if (tid < HID2) { ssc[tid] = g_scale[tid]; ssh[tid] = g_shift[tid]; }
    __syncthreads();

    int n = blockIdx.x * 8 + (tid >> 5);
    int lane = tid & 31;
    if (n >= N_NODES) return;

    float y0 = fmaxf(fmaf(g_z[n * HID2 + lane],      ssc[lane],      ssh[lane]),      0.f);
    float y1 = fmaxf(fmaf(g_z[n * HID2 + lane + 32], ssc[lane + 32], ssh[lane + 32]), 0.f);
    float acc = sb[lane];
#pragma unroll
    for (int j = 0; j < 32; j++) {
        acc = fmaf(__shfl_sync(FULL, y0, j), sw[j * HID + lane],        acc);
        acc = fmaf(__shfl_sync(FULL, y1, j), sw[(j + 32) * HID + lane], acc);
    }
    int base = n * HID + lane;
    g_h[base]  = fmaxf(acc, 0.f);   // outer relu from the layer loop
    g_dn[base] = make_float2(0.f, 0.f);
}

// ---------------- output projection: out = h @ w16 + b16 ---------------------
__global__ void k_final(const float* __restrict__ w16,
                        const float* __restrict__ b16,
                        float* __restrict__ out) {
    __shared__ float sw[HID * OUT_CH];
    __shared__ float sb[OUT_CH];
    int tid = threadIdx.x;
    for (int i = tid; i < HID * OUT_CH; i += 256) sw[i] = w16[i];
    if (tid < OUT_CH) sb[tid] = b16[tid];
    __syncthreads();

    int n = blockIdx.x * 8 + (tid >> 5);
    int lane = tid & 31;
    if (n >= N_NODES) return;

    float hv = g_h[n * HID + lane];
    float a0 = sb[lane], a1 = sb[lane + 32];
#pragma unroll
    for (int j = 0; j < 32; j++) {
        float hb = __shfl_sync(FULL, hv, j);
        a0 = fmaf(hb, sw[j * OUT_CH + lane],      a0);
        a1 = fmaf(hb, sw[j * OUT_CH + lane + 32], a1);
    }
    out[n * OUT_CH + lane]      = a0;
    out[n * OUT_CH + lane + 32] = a1;
}

// -----------------------------------------------------------------------------
extern "C" void kernel_launch(void* const* d_in, const int* in_sizes, int n_in,
                              void* d_out, int out_size) {
    const float* x      = (const float*)d_in[0];
    const int*   ei32   = (const int*)d_in[1];     // int32 OR int64 (detected)
    const float* w0     = (const float*)d_in[2];
    const float* b0     = (const float*)d_in[3];
    const float* lin1_w = (const float*)d_in[4];
    const float* lin1_b = (const float*)d_in[5];
    const float* gamma  = (const float*)d_in[6];
    const float* beta   = (const float*)d_in[7];
    const float* lin2_w = (const float*)d_in[8];
    const float* lin2_b = (const float*)d_in[9];
    const float* w16    = (const float*)d_in[10];
    const float* b16    = (const float*)d_in[11];
    float* out = (float*)d_out;

    const int nodeBlocks = (N_NODES + 7) / 8;                        // warp/node
    const int edgeBlocks = (N_EDGES / E_PER + 7) / 8;                // 8 warps/blk

    k_detect<<<1, 1024>>>(ei32);
    k_input<<<nodeBlocks, 256>>>(x, w0, b0);
    for (int i = 0; i < N_LAYERS; i++) {
        k_edge<<<edgeBlocks, 256>>>(ei32);
        k_mlp1<<<NBLK_MLP1, 256>>>(lin1_w + i * HID * HID2, lin1_b + i * HID2);
        k_bn<<<HID2, 256>>>(gamma + i * HID2, beta + i * HID2);
        k_mlp2<<<nodeBlocks, 256>>>(lin2_w + i * HID2 * HID, lin2_b + i * HID);
    }
    k_final<<<nodeBlocks, 256>>>(w16, b16, out);
}

// round 7
// speedup vs baseline: 3.3051x; 1.0550x over previous
#include <cuda_runtime.h>

#define N_NODES 100000
#define N_EDGES 1600000
#define IN_CH   128
#define HID     32
#define HID2    64
#define OUT_CH  64
#define N_LAYERS 16

#define EPS_MSG 1e-7f
#define EPS_SM  1e-16f
#define EPS_BN  1e-5f

#define FULL 0xffffffffu
#define NBLK_MLP1 1184
#define EW 8      // edges per warp in the edge pass (2 per half-warp step)

// ---------------- scratch (static device globals; no allocation) -------------
__device__ float  g_h [N_NODES * HID];    // current node features
__device__ float4 g_dn[N_NODES * 16];     // (den,num) x 2 channels per float4
__device__ float  g_z [N_NODES * HID2];   // hidden MLP activations
__device__ int2   g_edges[N_EDGES];       // preprocessed (src*16, dst*16)
__device__ float  g_psum[NBLK_MLP1 * HID2];
__device__ float  g_psq [NBLK_MLP1 * HID2];
__device__ float  g_scale[HID2];
__device__ float  g_shift[HID2];
__device__ int    g_is64;                 // 1 if edge_index is int64

// ---------------- detect edge_index dtype ------------------------------------
// int64 little-endian with values < 2^31 => every odd 32-bit word is 0.
__global__ void k_detect(const int* __restrict__ ei32) {
    __shared__ int any;
    if (threadIdx.x == 0) any = 0;
    __syncthreads();
    int v = ei32[2 * threadIdx.x + 1] | ei32[2 * (threadIdx.x + 1024) + 1];
    if (v != 0) any = 1;
    __syncthreads();
    if (threadIdx.x == 0) g_is64 = (any == 0) ? 1 : 0;
}

// ---------------- one-time edge preprocessing --------------------------------
// pack (src*16, dst*16), clamped, so the per-layer pass does zero index math
__global__ void k_prep(const int* __restrict__ ei32) {
    int e = blockIdx.x * 256 + threadIdx.x;
    if (e >= N_EDGES) return;
    int s, d;
    if (g_is64) { s = ei32[2 * e]; d = ei32[2 * (N_EDGES + e)]; }
    else        { s = ei32[e];     d = ei32[N_EDGES + e]; }
    s = min(max(s, 0), N_NODES - 1);
    d = min(max(d, 0), N_NODES - 1);
    g_edges[e] = make_int2(s * 16, d * 16);
}

// ---------------- input projection: h = x @ w0 + b0; zero accumulators -------
__global__ void k_input(const float* __restrict__ x,
                        const float* __restrict__ w0,
                        const float* __restrict__ b0) {
    __shared__ float sw[IN_CH * HID];
    __shared__ float sb[HID];
    int tid = threadIdx.x;
    for (int i = tid; i < IN_CH * HID; i += 256) sw[i] = w0[i];
    if (tid < HID) sb[tid] = b0[tid];
    __syncthreads();

    int n = blockIdx.x * 8 + (tid >> 5);
    int lane = tid & 31;
    if (n >= N_NODES) return;

    const float* xr = x + (long long)n * IN_CH;
    float acc = sb[lane];
#pragma unroll
    for (int k0 = 0; k0 < IN_CH; k0 += 32) {
        float xv = xr[k0 + lane];
#pragma unroll
        for (int j = 0; j < 32; j++) {
            float xb = __shfl_sync(FULL, xv, j);
            acc = fmaf(xb, sw[(k0 + j) * HID + lane], acc);
        }
    }
    g_h[n * HID + lane] = acc;
    ((float2*)g_dn)[n * HID + lane] = make_float2(0.f, 0.f);
}

// ---------------- single edge pass: den += e^m, num += e^m * m ---------------
// 2 channels per lane (float2 gather, v4 reduction); 2 edges per warp-step.
// No max subtraction: m = relu(h)+eps is O(10) (BN renormalizes every layer),
// so exp(m) cannot overflow and num/den is shift-invariant.
__global__ void k_edge() {
    int w = blockIdx.x * 8 + (threadIdx.x >> 5);
    int lane = threadIdx.x & 31;
    int cpair = lane & 15;
    int side = lane >> 4;
    int e0 = w * EW;
    if (e0 >= N_EDGES) return;

    const float2* __restrict__ h2 = (const float2*)g_h;

    int2 sd[EW / 2];
#pragma unroll
    for (int s = 0; s < EW / 2; s++)
        sd[s] = __ldg(&g_edges[e0 + 2 * s + side]);

    float2 hv[EW / 2];
#pragma unroll
    for (int s = 0; s < EW / 2; s++)
        hv[s] = h2[sd[s].x + cpair];

#pragma unroll
    for (int s = 0; s < EW / 2; s++) {
        float m0 = fmaxf(hv[s].x, 0.f) + EPS_MSG;
        float m1 = fmaxf(hv[s].y, 0.f) + EPS_MSG;
        float ex0 = __expf(m0);
        float ex1 = __expf(m1);
        float4* p = &g_dn[sd[s].y + cpair];
        asm volatile("red.global.add.v4.f32 [%0], {%1, %2, %3, %4};"
                     :: "l"(p), "f"(ex0), "f"(ex0 * m0),
                        "f"(ex1), "f"(ex1 * m1) : "memory");
    }
}

// ---------------- node MLP part 1: z = (agg + h) @ w1 + b1; BN partials ------
__global__ void k_mlp1(const float* __restrict__ w1,
                       const float* __restrict__ b1) {
    __shared__ float sw[HID * HID2];
    __shared__ float sb[HID2];
    __shared__ float bsum[HID2], bsq[HID2];
    int tid = threadIdx.x;
    for (int i = tid; i < HID * HID2; i += 256) sw[i] = w1[i];
    if (tid < HID2) { sb[tid] = b1[tid]; bsum[tid] = 0.f; bsq[tid] = 0.f; }
    __syncthreads();

    const float2* __restrict__ dn2 = (const float2*)g_dn;
    int lane = tid & 31;
    int warp = blockIdx.x * 8 + (tid >> 5);
    int nwarps = gridDim.x * 8;
    float s0 = 0.f, q0 = 0.f, s1 = 0.f, q1 = 0.f;

    for (int n = warp; n < N_NODES; n += nwarps) {
        int base = n * HID + lane;
        float2 dn = dn2[base];
        float ov = dn.y / (dn.x + EPS_SM) + g_h[base];
        float a0 = sb[lane], a1 = sb[lane + 32];
#pragma unroll
        for (int j = 0; j < 32; j++) {
            float ob = __shfl_sync(FULL, ov, j);
            a0 = fmaf(ob, sw[j * HID2 + lane],      a0);
            a1 = fmaf(ob, sw[j * HID2 + lane + 32], a1);
        }
        g_z[n * HID2 + lane]      = a0;
        g_z[n * HID2 + lane + 32] = a1;
        s0 += a0; q0 += a0 * a0;
        s1 += a1; q1 += a1 * a1;
    }
    atomicAdd(&bsum[lane],      s0); atomicAdd(&bsq[lane],      q0);
    atomicAdd(&bsum[lane + 32], s1); atomicAdd(&bsq[lane + 32], q1);
    __syncthreads();
    if (tid < HID2) {
        g_psum[blockIdx.x * HID2 + tid] = bsum[tid];
        g_psq [blockIdx.x * HID2 + tid] = bsq[tid];
    }
}

// ---------------- BN finalize: reduce partials; fold into scale/shift --------
__global__ void k_bn(const float* __restrict__ gamma,
                     const float* __restrict__ beta) {
    __shared__ float rs[256], rq[256];
    int c = blockIdx.x;
    int tid = threadIdx.x;
    float s = 0.f, q = 0.f;
    for (int b = tid; b < NBLK_MLP1; b += 256) {
        s += g_psum[b * HID2 + c];
        q += g_psq [b * HID2 + c];
    }
    rs[tid] = s; rq[tid] = q;
    __syncthreads();
    for (int o = 128; o > 0; o >>= 1) {
        if (tid < o) { rs[tid] += rs[tid + o]; rq[tid] += rq[tid + o]; }
        __syncthreads();
    }
    if (tid == 0) {
        float mean = rs[0] / (float)N_NODES;
        float var  = rq[0] / (float)N_NODES - mean * mean;
        float rstd = rsqrtf(var + EPS_BN);
        float sc = gamma[c] * rstd;
        g_scale[c] = sc;
        g_shift[c] = beta[c] - mean * sc;
    }
}

// ---------------- node MLP part 2: h = relu(relu(BN(z)) @ w2 + b2) -----------
// also zeroes the per-node accumulators for the next layer's edge pass
__global__ void k_mlp2(const float* __restrict__ w2,
                       const float* __restrict__ b2) {
    __shared__ float sw[HID2 * HID];
    __shared__ float sb[HID];
    __shared__ float ssc[HID2], ssh[HID2];
    int tid = threadIdx.x;
    for (int i = tid; i < HID2 * HID; i += 256) sw[i] = w2[i];
    if (tid < HID) sb[tid] = b2[tid];
    if (tid < HID2) { ssc[tid] = g_scale[tid]; ssh[tid] = g_shift[tid]; }
    __syncthreads();

    int n = blockIdx.x * 8 + (tid >> 5);
    int lane = tid & 31;
    if (n >= N_NODES) return;

    float y0 = fmaxf(fmaf(g_z[n * HID2 + lane],      ssc[lane],      ssh[lane]),      0.f);
    float y1 = fmaxf(fmaf(g_z[n * HID2 + lane + 32], ssc[lane + 32], ssh[lane + 32]), 0.f);
    float acc = sb[lane];
#pragma unroll
    for (int j = 0; j < 32; j++) {
        acc = fmaf(__shfl_sync(FULL, y0, j), sw[j * HID + lane],        acc);
        acc = fmaf(__shfl_sync(FULL, y1, j), sw[(j + 32) * HID + lane], acc);
    }
    g_h[n * HID + lane] = fmaxf(acc, 0.f);   // outer relu from the layer loop
    ((float2*)g_dn)[n * HID + lane] = make_float2(0.f, 0.f);
}

// ---------------- output projection: out = h @ w16 + b16 ---------------------
__global__ void k_final(const float* __restrict__ w16,
                        const float* __restrict__ b16,
                        float* __restrict__ out) {
    __shared__ float sw[HID * OUT_CH];
    __shared__ float sb[OUT_CH];
    int tid = threadIdx.x;
    for (int i = tid; i < HID * OUT_CH; i += 256) sw[i] = w16[i];
    if (tid < OUT_CH) sb[tid] = b16[tid];
    __syncthreads();

    int n = blockIdx.x * 8 + (tid >> 5);
    int lane = tid & 31;
    if (n >= N_NODES) return;

    float hv = g_h[n * HID + lane];
    float a0 = sb[lane], a1 = sb[lane + 32];
#pragma unroll
    for (int j = 0; j < 32; j++) {
        float hb = __shfl_sync(FULL, hv, j);
        a0 = fmaf(hb, sw[j * OUT_CH + lane],      a0);
        a1 = fmaf(hb, sw[j * OUT_CH + lane + 32], a1);
    }
    out[n * OUT_CH + lane]      = a0;
    out[n * OUT_CH + lane + 32] = a1;
}

// -----------------------------------------------------------------------------
extern "C" void kernel_launch(void* const* d_in, const int* in_sizes, int n_in,
                              void* d_out, int out_size) {
    const float* x      = (const float*)d_in[0];
    const int*   ei32   = (const int*)d_in[1];     // int32 OR int64 (detected)
    const float* w0     = (const float*)d_in[2];
    const float* b0     = (const float*)d_in[3];
    const float* lin1_w = (const float*)d_in[4];
    const float* lin1_b = (const float*)d_in[5];
    const float* gamma  = (const float*)d_in[6];
    const float* beta   = (const float*)d_in[7];
    const float* lin2_w = (const float*)d_in[8];
    const float* lin2_b = (const float*)d_in[9];
    const float* w16    = (const float*)d_in[10];
    const float* b16    = (const float*)d_in[11];
    float* out = (float*)d_out;

    const int nodeBlocks = (N_NODES + 7) / 8;                  // warp per node
    const int edgeBlocks = N_EDGES / (8 * EW);                 // 8 warps/block
    const int prepBlocks = (N_EDGES + 255) / 256;

    k_detect<<<1, 1024>>>(ei32);
    k_prep<<<prepBlocks, 256>>>(ei32);
    k_input<<<nodeBlocks, 256>>>(x, w0, b0);
    for (int i = 0; i < N_LAYERS; i++) {
        k_edge<<<edgeBlocks, 256>>>();
        k_mlp1<<<NBLK_MLP1, 256>>>(lin1_w + i * HID * HID2, lin1_b + i * HID2);
        k_bn<<<HID2, 256>>>(gamma + i * HID2, beta + i * HID2);
        k_mlp2<<<nodeBlocks, 256>>>(lin2_w + i * HID2 * HID, lin2_b + i * HID);
    }
    k_final<<<nodeBlocks, 256>>>(w16, b16, out);
}

// round 8
// speedup vs baseline: 3.5640x; 1.0783x over previous
#include <cuda_runtime.h>

#define N_NODES 100000
#define N_EDGES 1600000
#define IN_CH   128
#define HID     32
#define HID2    64
#define OUT_CH  64
#define N_LAYERS 16

#define EPS_MSG 1e-7f
#define EPS_SM  1e-16f
#define EPS_BN  1e-5f

#define FULL 0xffffffffu
#define NBLK_F 12500   // fused kernel blocks: 8 warps/block, warp per node

// ---------------- scratch (static device globals; no allocation) -------------
__device__ float g_h [N_NODES * HID];     // current node features
__device__ float g_z [N_NODES * HID2];    // hidden MLP activations
__device__ int   g_deg[N_NODES];          // in-degree (prep)
__device__ int   g_off[N_NODES + 1];      // CSR offsets by dst
__device__ int   g_cur[N_NODES];          // fill cursors
__device__ int   g_srcs[N_EDGES];         // CSR: src*16 per edge, grouped by dst
__device__ float g_psum[NBLK_F * HID2];   // BN partial sums
__device__ float g_psq [NBLK_F * HID2];   // BN partial sum-squares
__device__ float g_scale[HID2];
__device__ float g_shift[HID2];
__device__ int   g_is64;                  // 1 if edge_index is int64

// ---------------- detect edge_index dtype ------------------------------------
// int64 little-endian with values < 2^31 => every odd 32-bit word is 0.
__global__ void k_detect(const int* __restrict__ ei32) {
    __shared__ int any;
    if (threadIdx.x == 0) any = 0;
    __syncthreads();
    int v = ei32[2 * threadIdx.x + 1] | ei32[2 * (threadIdx.x + 1024) + 1];
    if (v != 0) any = 1;
    __syncthreads();
    if (threadIdx.x == 0) g_is64 = (any == 0) ? 1 : 0;
}

// ---------------- one-time CSR build -----------------------------------------
__global__ void k_zero_deg() {
    int i = blockIdx.x * 256 + threadIdx.x;
    if (i < N_NODES) g_deg[i] = 0;
}

__device__ __forceinline__ void raw_edge(const int* __restrict__ ei32,
                                         int e, int& s, int& d) {
    if (g_is64) { s = ei32[2 * e]; d = ei32[2 * (N_EDGES + e)]; }
    else        { s = ei32[e];     d = ei32[N_EDGES + e]; }
    s = min(max(s, 0), N_NODES - 1);
    d = min(max(d, 0), N_NODES - 1);
}

__global__ void k_deg(const int* __restrict__ ei32) {
    int e = blockIdx.x * 256 + threadIdx.x;
    if (e >= N_EDGES) return;
    int s, d; raw_edge(ei32, e, s, d);
    atomicAdd(&g_deg[d], 1);
}

// single-block exclusive scan of g_deg -> g_off (and g_cur)
__global__ void k_scan() {
    __shared__ int tmp[1024];
    __shared__ int carry;
    int tid = threadIdx.x;
    if (tid == 0) carry = 0;
    __syncthreads();
    for (int base = 0; base < N_NODES; base += 1024) {
        int i = base + tid;
        int v = (i < N_NODES) ? g_deg[i] : 0;
        tmp[tid] = v;
        __syncthreads();
        for (int o = 1; o < 1024; o <<= 1) {
            int t = (tid >= o) ? tmp[tid - o] : 0;
            __syncthreads();
            tmp[tid] += t;
            __syncthreads();
        }
        int excl = tmp[tid] - v + carry;
        if (i < N_NODES) { g_off[i] = excl; g_cur[i] = excl; }
        __syncthreads();
        if (tid == 0) carry += tmp[1023];
        __syncthreads();
    }
    if (tid == 0) g_off[N_NODES] = carry;
}

__global__ void k_fill(const int* __restrict__ ei32) {
    int e = blockIdx.x * 256 + threadIdx.x;
    if (e >= N_EDGES) return;
    int s, d; raw_edge(ei32, e, s, d);
    int p = atomicAdd(&g_cur[d], 1);
    g_srcs[p] = s * 16;      // pre-scaled for float2 indexing
}

// ---------------- input projection: h = x @ w0 + b0 --------------------------
__global__ void k_input(const float* __restrict__ x,
                        const float* __restrict__ w0,
                        const float* __restrict__ b0) {
    __shared__ float sw[IN_CH * HID];
    __shared__ float sb[HID];
    int tid = threadIdx.x;
    for (int i = tid; i < IN_CH * HID; i += 256) sw[i] = w0[i];
    if (tid < HID) sb[tid] = b0[tid];
    __syncthreads();

    int n = blockIdx.x * 8 + (tid >> 5);
    int lane = tid & 31;
    if (n >= N_NODES) return;

    const float* xr = x + (long long)n * IN_CH;
    float acc = sb[lane];
#pragma unroll
    for (int k0 = 0; k0 < IN_CH; k0 += 32) {
        float xv = xr[k0 + lane];
#pragma unroll
        for (int j = 0; j < 32; j++) {
            float xb = __shfl_sync(FULL, xv, j);
            acc = fmaf(xb, sw[(k0 + j) * HID + lane], acc);
        }
    }
    g_h[n * HID + lane] = acc;
}

// ---------------- fused edge aggregation + MLP1 + BN partials ----------------
// Warp per dst node. CSR gather: half-warp per edge, 2 channels per lane.
// No max subtraction: m = relu(h)+eps is O(10) (BN renormalizes every layer),
// so exp(m) cannot overflow and num/den is shift-invariant.
// After register-resident softmax sums, the same warp computes
// z = (num/den + h) @ w1 + b1 and accumulates BN partial stats.
__global__ void k_fused(const float* __restrict__ w1,
                        const float* __restrict__ b1) {
    __shared__ float sw[HID * HID2];
    __shared__ float sb[HID2];
    __shared__ float bsum[HID2], bsq[HID2];
    int tid = threadIdx.x;
    for (int i = tid; i < HID * HID2; i += 256) sw[i] = w1[i];
    if (tid < HID2) { sb[tid] = b1[tid]; bsum[tid] = 0.f; bsq[tid] = 0.f; }
    __syncthreads();

    int n = blockIdx.x * 8 + (tid >> 5);
    int lane = tid & 31;
    float s0 = 0.f, q0 = 0.f, s1 = 0.f, q1 = 0.f;

    if (n < N_NODES) {
        int cp   = lane & 15;      // channel pair 0..15
        int half = lane >> 4;      // which edge of the pair
        int beg = g_off[n];
        int end = g_off[n + 1];
        const float2* __restrict__ h2 = (const float2*)g_h;

        float d0 = 0.f, m0s = 0.f, d1 = 0.f, m1s = 0.f;
        int i = beg + half;
        // 2-way unroll: two independent gathers in flight per lane
        for (; i + 2 < end; i += 4) {
            int sA = g_srcs[i];
            int sB = g_srcs[i + 2];
            float2 hA = h2[sA + cp];
            float2 hB = h2[sB + cp];
            float a0 = fmaxf(hA.x, 0.f) + EPS_MSG;
            float a1 = fmaxf(hA.y, 0.f) + EPS_MSG;
            float b0v = fmaxf(hB.x, 0.f) + EPS_MSG;
            float b1v = fmaxf(hB.y, 0.f) + EPS_MSG;
            float eA0 = __expf(a0), eA1 = __expf(a1);
            float eB0 = __expf(b0v), eB1 = __expf(b1v);
            d0 += eA0 + eB0;  m0s += eA0 * a0 + eB0 * b0v;
            d1 += eA1 + eB1;  m1s += eA1 * a1 + eB1 * b1v;
        }
        for (; i < end; i += 2) {
            int sA = g_srcs[i];
            float2 hA = h2[sA + cp];
            float a0 = fmaxf(hA.x, 0.f) + EPS_MSG;
            float a1 = fmaxf(hA.y, 0.f) + EPS_MSG;
            float eA0 = __expf(a0), eA1 = __expf(a1);
            d0 += eA0;  m0s += eA0 * a0;
            d1 += eA1;  m1s += eA1 * a1;
        }
        // combine the two half-warps
        d0  += __shfl_xor_sync(FULL, d0, 16);
        m0s += __shfl_xor_sync(FULL, m0s, 16);
        d1  += __shfl_xor_sync(FULL, d1, 16);
        m1s += __shfl_xor_sync(FULL, m1s, 16);

        float2 hv = h2[n * 16 + cp];
        float ov0 = m0s / (d0 + EPS_SM) + hv.x;   // channel 2*cp
        float ov1 = m1s / (d1 + EPS_SM) + hv.y;   // channel 2*cp+1

        // GEMM: z[n, :] = ov @ w1 + b1 ; lane c handles outputs c and c+32
        float a0 = sb[lane], a1 = sb[lane + 32];
#pragma unroll
        for (int q = 0; q < 16; q++) {
            float o0 = __shfl_sync(FULL, ov0, q);
            float o1 = __shfl_sync(FULL, ov1, q);
            a0 = fmaf(o0, sw[(2 * q) * HID2 + lane],          a0);
            a1 = fmaf(o0, sw[(2 * q) * HID2 + lane + 32],     a1);
            a0 = fmaf(o1, sw[(2 * q + 1) * HID2 + lane],      a0);
            a1 = fmaf(o1, sw[(2 * q + 1) * HID2 + lane + 32], a1);
        }
        g_z[n * HID2 + lane]      = a0;
        g_z[n * HID2 + lane + 32] = a1;
        s0 = a0; q0 = a0 * a0;
        s1 = a1; q1 = a1 * a1;
    }

    atomicAdd(&bsum[lane],      s0); atomicAdd(&bsq[lane],      q0);
    atomicAdd(&bsum[lane + 32], s1); atomicAdd(&bsq[lane + 32], q1);
    __syncthreads();
    if (tid < HID2) {
        g_psum[blockIdx.x * HID2 + tid] = bsum[tid];
        g_psq [blockIdx.x * HID2 + tid] = bsq[tid];
    }
}

// ---------------- BN finalize: reduce partials; fold into scale/shift --------
__global__ void k_bn(const float* __restrict__ gamma,
                     const float* __restrict__ beta) {
    __shared__ float rs[256], rq[256];
    int c = blockIdx.x;
    int tid = threadIdx.x;
    float s = 0.f, q = 0.f;
    for (int b = tid; b < NBLK_F; b += 256) {
        s += g_psum[b * HID2 + c];
        q += g_psq [b * HID2 + c];
    }
    rs[tid] = s; rq[tid] = q;
    __syncthreads();
    for (int o = 128; o > 0; o >>= 1) {
        if (tid < o) { rs[tid] += rs[tid + o]; rq[tid] += rq[tid + o]; }
        __syncthreads();
    }
    if (tid == 0) {
        float mean = rs[0] / (float)N_NODES;
        float var  = rq[0] / (float)N_NODES - mean * mean;
        float rstd = rsqrtf(var + EPS_BN);
        float sc = gamma[c] * rstd;
        g_scale[c] = sc;
        g_shift[c] = beta[c] - mean * sc;
    }
}

// ---------------- node MLP part 2: h = relu(relu(BN(z)) @ w2 + b2) -----------
__global__ void k_mlp2(const float* __restrict__ w2,
                       const float* __restrict__ b2) {
    __shared__ float sw[HID2 * HID];
    __shared__ float sb[HID];
    __shared__ float ssc[HID2], ssh[HID2];
    int tid = threadIdx.x;
    for (int i = tid; i < HID2 * HID; i += 256) sw[i] = w2[i];
    if (tid < HID) sb[tid] = b2[tid];
    if (tid < HID2) { ssc[tid] = g_scale[tid]; ssh[tid] = g_shift[tid]; }
    __syncthreads();

    int n = blockIdx.x * 8 + (tid >> 5);
    int lane = tid & 31;
    if (n >= N_NODES) return;

    float y0 = fmaxf(fmaf(g_z[n * HID2 + lane],      ssc[lane],      ssh[lane]),      0.f);
    float y1 = fmaxf(fmaf(g_z[n * HID2 + lane + 32], ssc[lane + 32], ssh[lane + 32]), 0.f);
    float acc = sb[lane];
#pragma unroll
    for (int j = 0; j < 32; j++) {
        acc = fmaf(__shfl_sync(FULL, y0, j), sw[j * HID + lane],        acc);
        acc = fmaf(__shfl_sync(FULL, y1, j), sw[(j + 32) * HID + lane], acc);
    }
    g_h[n * HID + lane] = fmaxf(acc, 0.f);   // outer relu from the layer loop
}

// ---------------- output projection: out = h @ w16 + b16 ---------------------
__global__ void k_final(const float* __restrict__ w16,
                        const float* __restrict__ b16,
                        float* __restrict__ out) {
    __shared__ float sw[HID * OUT_CH];
    __shared__ float sb[OUT_CH];
    int tid = threadIdx.x;
    for (int i = tid; i < HID * OUT_CH; i += 256) sw[i] = w16[i];
    if (tid < OUT_CH) sb[tid] = b16[tid];
    __syncthreads();

    int n = blockIdx.x * 8 + (tid >> 5);
    int lane = tid & 31;
    if (n >= N_NODES) return;

    float hv = g_h[n * HID + lane];
    float a0 = sb[lane], a1 = sb[lane + 32];
#pragma unroll
    for (int j = 0; j < 32; j++) {
        float hb = __shfl_sync(FULL, hv, j);
        a0 = fmaf(hb, sw[j * OUT_CH + lane],      a0);
        a1 = fmaf(hb, sw[j * OUT_CH + lane + 32], a1);
    }
    out[n * OUT_CH + lane]      = a0;
    out[n * OUT_CH + lane + 32] = a1;
}

// -----------------------------------------------------------------------------
extern "C" void kernel_launch(void* const* d_in, const int* in_sizes, int n_in,
                              void* d_out, int out_size) {
    const float* x      = (const float*)d_in[0];
    const int*   ei32   = (const int*)d_in[1];     // int32 OR int64 (detected)
    const float* w0     = (const float*)d_in[2];
    const float* b0     = (const float*)d_in[3];
    const float* lin1_w = (const float*)d_in[4];
    const float* lin1_b = (const float*)d_in[5];
    const float* gamma  = (const float*)d_in[6];
    const float* beta   = (const float*)d_in[7];
    const float* lin2_w = (const float*)d_in[8];
    const float* lin2_b = (const float*)d_in[9];
    const float* w16    = (const float*)d_in[10];
    const float* b16    = (const float*)d_in[11];
    float* out = (float*)d_out;

    const int nodeBlocks = (N_NODES + 7) / 8;        // warp per node
    const int edgeBlocks = (N_EDGES + 255) / 256;

    // one-time per call: dtype detect + CSR build
    k_detect<<<1, 1024>>>(ei32);
    k_zero_deg<<<(N_NODES + 255) / 256, 256>>>();
    k_deg<<<edgeBlocks, 256>>>(ei32);
    k_scan<<<1, 1024>>>();
    k_fill<<<edgeBlocks, 256>>>(ei32);

    k_input<<<nodeBlocks, 256>>>(x, w0, b0);
    for (int i = 0; i < N_LAYERS; i++) {
        k_fused<<<NBLK_F, 256>>>(lin1_w + i * HID * HID2, lin1_b + i * HID2);
        k_bn<<<HID2, 256>>>(gamma + i * HID2, beta + i * HID2);
        k_mlp2<<<nodeBlocks, 256>>>(lin2_w + i * HID2 * HID, lin2_b + i * HID);
    }
    k_final<<<nodeBlocks, 256>>>(w16, b16, out);
}